// round 7
// baseline (speedup 1.0000x reference)
#include <cuda_runtime.h>
#include <cuda_bf16.h>
#include <cstdint>

#define BB 16
#define LL 2048
#define DDIM 64
#define MT 128          // q rows per CTA
#define NTILE 128       // k cols per tile
#define NTHREADS 256
#define NIT 32          // 2 passes x 16 tiles
#define LOG2E 1.4426950408889634f

// k split-precision scratch
__device__ __nv_bfloat16 g_k_hi[BB * LL * DDIM];
__device__ __nv_bfloat16 g_k_lo[BB * LL * DDIM];

// ---------------- PTX helpers (generic-target safe) ----------------
__device__ __forceinline__ void cp16(uint32_t dst, const void* src) {
    asm volatile("cp.async.cg.shared.global [%0], [%1], 16;\n" :: "r"(dst), "l"(src));
}
__device__ __forceinline__ void cp_commit() {
    asm volatile("cp.async.commit_group;\n");
}
template <int N>
__device__ __forceinline__ void cp_wait() {
    asm volatile("cp.async.wait_group %0;\n" :: "n"(N));
}
__device__ __forceinline__ float ex2(float x) {
    float r;
    asm("ex2.approx.f32 %0, %1;" : "=f"(r) : "f"(x));
    return r;
}

#define LDSM4(r0, r1, r2, r3, addr)                                        \
    asm volatile("ldmatrix.sync.aligned.m8n8.x4.shared.b16 {%0,%1,%2,%3}, [%4];" \
                 : "=r"(r0), "=r"(r1), "=r"(r2), "=r"(r3) : "r"(addr))

#define MMA_BF16(c, a, b0, b1)                                             \
    asm volatile("mma.sync.aligned.m16n8k16.row.col.f32.bf16.bf16.f32 "    \
                 "{%0,%1,%2,%3}, {%4,%5,%6,%7}, {%8,%9}, {%0,%1,%2,%3};"   \
                 : "+f"((c)[0]), "+f"((c)[1]), "+f"((c)[2]), "+f"((c)[3])  \
                 : "r"((a)[0]), "r"((a)[1]), "r"((a)[2]), "r"((a)[3]),     \
                   "r"(b0), "r"(b1))

__device__ __forceinline__ uint32_t pack2(float a, float b) {
    __nv_bfloat162 t = __floats2bfloat162_rn(a, b);
    return *reinterpret_cast<uint32_t*>(&t);
}
__device__ __forceinline__ uint32_t pack_hi(float2 f) {
    return pack2(f.x, f.y);
}
__device__ __forceinline__ uint32_t pack_lo(float2 f) {
    float hx = __bfloat162float(__float2bfloat16_rn(f.x));
    float hy = __bfloat162float(__float2bfloat16_rn(f.y));
    return pack2(f.x - hx, f.y - hy);
}

// ---------------- kernel 1: k fp32 -> bf16 hi/lo scratch ----------------
__global__ void __launch_bounds__(256)
cvt_k_kernel(const float4* __restrict__ k4) {
    int idx = blockIdx.x * 256 + threadIdx.x;
    float4 f = k4[idx];
    float hx = __bfloat162float(__float2bfloat16_rn(f.x));
    float hy = __bfloat162float(__float2bfloat16_rn(f.y));
    float hz = __bfloat162float(__float2bfloat16_rn(f.z));
    float hw = __bfloat162float(__float2bfloat16_rn(f.w));
    uint2 hi, lo;
    hi.x = pack2(f.x, f.y);            hi.y = pack2(f.z, f.w);
    lo.x = pack2(f.x - hx, f.y - hy);  lo.y = pack2(f.z - hz, f.w - hw);
    reinterpret_cast<uint2*>(g_k_hi)[idx] = hi;
    reinterpret_cast<uint2*>(g_k_lo)[idx] = lo;
}

// ---------------- k tile loader: [buf:3][mat:2][n:128][128B], swizzled -----
__device__ __forceinline__ void load_k_tile(uint32_t sb, int b, int tile,
                                            int buf, int tid) {
    const size_t base = ((size_t)b * LL + (size_t)tile * NTILE) * DDIM;
    #pragma unroll
    for (int rep = 0; rep < 8; rep++) {
        const int m = rep >> 2;                      // 0=hi, 1=lo
        int cidx = tid + (rep & 3) * NTHREADS;       // 0..1023 per matrix
        int n = cidx >> 3, ch = cidx & 7;
        const __nv_bfloat16* src =
            (m ? g_k_lo : g_k_hi) + base + (size_t)n * DDIM + ch * 8;
        uint32_t dst = sb + (uint32_t)buf * 32768u + (uint32_t)m * 16384u
                     + (uint32_t)n * 128u + (uint32_t)((ch ^ (n & 7)) << 4);
        cp16(dst, src);
    }
}

// ---------------- kernel 2: attention ----------------
__global__ void __launch_bounds__(NTHREADS, 2)
attn_mma_kernel(const float* __restrict__ q, float* __restrict__ out_attn) {
    extern __shared__ char smem[];
    const uint32_t sb = (uint32_t)__cvta_generic_to_shared(smem);
    const int tid = threadIdx.x;
    const int w = tid >> 5;
    const int l = tid & 31;
    const int b = blockIdx.y;
    const int qt = blockIdx.x;

    // prologue: tiles 0,1 in flight
    load_k_tile(sb, b, 0, 0, tid);
    cp_commit();
    load_k_tile(sb, b, 1, 1, tid);
    cp_commit();

    // A fragments (q pre-scaled by log2e, split hi/lo)
    uint32_t ahi[4][4], alo[4][4];
    {
        const float* q0 = q + ((size_t)b * LL + (size_t)qt * MT
                               + w * 16 + (l >> 2)) * DDIM;
        #pragma unroll
        for (int ks = 0; ks < 4; ks++) {
            const int c0 = ks * 16 + (l & 3) * 2;
            float2 p00 = *(const float2*)(q0 + c0);
            float2 p10 = *(const float2*)(q0 + 8 * DDIM + c0);
            float2 p01 = *(const float2*)(q0 + c0 + 8);
            float2 p11 = *(const float2*)(q0 + 8 * DDIM + c0 + 8);
            p00.x *= LOG2E; p00.y *= LOG2E;
            p10.x *= LOG2E; p10.y *= LOG2E;
            p01.x *= LOG2E; p01.y *= LOG2E;
            p11.x *= LOG2E; p11.y *= LOG2E;
            ahi[ks][0] = pack_hi(p00);  alo[ks][0] = pack_lo(p00);
            ahi[ks][1] = pack_hi(p10);  alo[ks][1] = pack_lo(p10);
            ahi[ks][2] = pack_hi(p01);  alo[ks][2] = pack_lo(p01);
            ahi[ks][3] = pack_hi(p11);  alo[ks][3] = pack_lo(p11);
        }
    }

    // per-lane ldmatrix pieces
    const int rr = l & 7;
    const int mi = l >> 3;
    const int cs = mi & 1;
    const int nb = ((mi >> 1) << 3) + rr;

    float s00 = 0.f, s01 = 0.f, s10 = 0.f, s11 = 0.f;
    float inv0 = 0.f, inv1 = 0.f;
    float* orow0 = out_attn + ((size_t)b * LL + (size_t)qt * MT
                               + w * 16 + (l >> 2)) * (size_t)LL;
    float* orow1 = orow0 + (size_t)8 * LL;

    for (int it = 0; it < NIT; it++) {
        const int buf = it % 3;
        const int tile = it & 15;

        cp_wait<1>();
        __syncthreads();

        // issue load(t+2) into buf (t+2)%3 — never read by any warp this iter
        if (it + 2 < NIT)
            load_k_tile(sb, b, (it + 2) & 15, (it + 2) % 3, tid);
        cp_commit();   // uniform one group per iter keeps wait<1> exact

        const uint32_t bhiB = sb + (uint32_t)buf * 32768u;
        const uint32_t bloB = bhiB + 16384u;

        #pragma unroll
        for (int half = 0; half < 2; half++) {
            float C[8][4];
            #pragma unroll
            for (int i = 0; i < 8; i++)
                C[i][0] = C[i][1] = C[i][2] = C[i][3] = 0.f;

            #pragma unroll
            for (int ks = 0; ks < 4; ks++) {
                const uint32_t choff =
                    (uint32_t)((((ks << 1) | cs) ^ rr) << 4);

                uint32_t f0[4], f1[4], f2[4], f3[4];

                // ---- hi B-frags for all 4 n16-groups, then 16 round-robin MMAs
                #pragma unroll
                for (int j = 0; j < 4; j++) {
                    const uint32_t rowoff =
                        (uint32_t)(half * 64 + j * 16 + nb) * 128u;
                    LDSM4(f0[j], f1[j], f2[j], f3[j], bhiB + rowoff + choff);
                }
                #pragma unroll
                for (int j = 0; j < 4; j++)
                    MMA_BF16(C[2 * j], ahi[ks], f0[j], f1[j]);
                #pragma unroll
                for (int j = 0; j < 4; j++)
                    MMA_BF16(C[2 * j + 1], ahi[ks], f2[j], f3[j]);
                #pragma unroll
                for (int j = 0; j < 4; j++)
                    MMA_BF16(C[2 * j], alo[ks], f0[j], f1[j]);
                #pragma unroll
                for (int j = 0; j < 4; j++)
                    MMA_BF16(C[2 * j + 1], alo[ks], f2[j], f3[j]);

                // ---- lo B-frags, 8 more round-robin MMAs
                #pragma unroll
                for (int j = 0; j < 4; j++) {
                    const uint32_t rowoff =
                        (uint32_t)(half * 64 + j * 16 + nb) * 128u;
                    LDSM4(f0[j], f1[j], f2[j], f3[j], bloB + rowoff + choff);
                }
                #pragma unroll
                for (int j = 0; j < 4; j++)
                    MMA_BF16(C[2 * j], ahi[ks], f0[j], f1[j]);
                #pragma unroll
                for (int j = 0; j < 4; j++)
                    MMA_BF16(C[2 * j + 1], ahi[ks], f2[j], f3[j]);
            }

            if (it < 16) {
                #pragma unroll
                for (int nf = 0; nf < 8; nf++) {
                    s00 += ex2(C[nf][0]);
                    s01 += ex2(C[nf][1]);
                    s10 += ex2(C[nf][2]);
                    s11 += ex2(C[nf][3]);
                }
            } else {
                const int colb = tile * NTILE + half * 64 + ((l & 3) << 1);
                #pragma unroll
                for (int nf = 0; nf < 8; nf++) {
                    float2 v0, v1;
                    v0.x = ex2(C[nf][0]) * inv0;
                    v0.y = ex2(C[nf][1]) * inv0;
                    v1.x = ex2(C[nf][2]) * inv1;
                    v1.y = ex2(C[nf][3]) * inv1;
                    *(float2*)(orow0 + colb + nf * 8) = v0;
                    *(float2*)(orow1 + colb + nf * 8) = v1;
                }
            }
        }

        if (it == 15) {
            float sum0 = s00 + s01;
            float sum1 = s10 + s11;
            sum0 += __shfl_xor_sync(0xFFFFFFFFu, sum0, 1);
            sum0 += __shfl_xor_sync(0xFFFFFFFFu, sum0, 2);
            sum1 += __shfl_xor_sync(0xFFFFFFFFu, sum1, 1);
            sum1 += __shfl_xor_sync(0xFFFFFFFFu, sum1, 2);
            inv0 = 1.0f / sum0;
            inv1 = 1.0f / sum1;
        }
    }
}

extern "C" void kernel_launch(void* const* d_in, const int* in_sizes, int n_in,
                              void* d_out, int out_size) {
    const float* q = (const float*)d_in[0];
    const float* k = (const float*)d_in[1];
    const float* v = (const float*)d_in[2];
    float* out = (float*)d_out;

    const size_t v_elems = (size_t)BB * LL * DDIM;
    cudaMemcpyAsync(out, v, v_elems * sizeof(float), cudaMemcpyDeviceToDevice);

    cvt_k_kernel<<<(BB * LL * DDIM / 4) / 256, 256>>>((const float4*)k);

    cudaFuncSetAttribute(attn_mma_kernel,
                         cudaFuncAttributeMaxDynamicSharedMemorySize, 98304);
    dim3 grid(LL / MT, BB);   // (16, 16) = 256 CTAs
    attn_mma_kernel<<<grid, NTHREADS, 98304>>>(q, out + v_elems);
}